// round 9
// baseline (speedup 1.0000x reference)
#include <cuda_runtime.h>

#define FULLMASK 0xFFFFFFFFu

constexpr int   G     = 64;          // 64x64 grid of 16px cells
constexpr float CELL  = 16.0f;
constexpr float CELLI = 1.0f / 16.0f;
constexpr int   NC    = G * G;
constexpr int   R     = 4;           // replicated sub-counters per cell (contention /4)
constexpr int   SUB   = 28;          // capacity per replica; lambda=4 -> P(>28) ~ 4e-17
constexpr int   CAP   = R * SUB;     // 112 slots per cell
constexpr int   K     = 9;
constexpr int   WARPS = 2;
constexpr int   CHUNK = 6;           // 6*32 = 192 capacity; P(T>192) ~ 3e-5

__device__ int    g_count[NC * R];     // [cell][replica]
__device__ float4 g_cells[NC * CAP];   // x, y, bitcast(orig idx), pad

__global__ void bin_k(const float* __restrict__ p, int N) {
    int i0 = blockIdx.x * blockDim.x + threadIdx.x;
    int half = N >> 1;
    #pragma unroll
    for (int kk = 0; kk < 2; kk++) {     // 2 independent chains per thread (MLP)
        int i = i0 + kk * half;
        if (i < N) {
            float2 c = reinterpret_cast<const float2*>(p)[i * 3 + 1];  // floats 6i+2,6i+3
            int cx = min(G - 1, max(0, (int)(c.x * CELLI)));
            int cy = min(G - 1, max(0, (int)(c.y * CELLI)));
            int cell = cy * G + cx;
            int r = i & (R - 1);
            int pos = atomicAdd(&g_count[cell * R + r], 1);
            if (pos < SUB)
                g_cells[cell * CAP + r * SUB + pos] =
                    make_float4(c.x, c.y, __int_as_float(i), 0.f);
        }
    }
}

__global__ __launch_bounds__(WARPS * 32, 8)
void atss_search_k(const float* __restrict__ pbox,
                   const float* __restrict__ tgt,
                   float* __restrict__ out, int NT)
{
    const int lane = threadIdx.x & 31;
    const int t = blockIdx.x * WARPS + (threadIdx.x >> 5);
    if (t >= NT) return;

    const float INF = __int_as_float(0x7f800000);
    float2 tc = *reinterpret_cast<const float2*>(tgt + t * 6 + 2);
    float2 ts = *reinterpret_cast<const float2*>(tgt + t * 6 + 4);
    const float tx = tc.x, ty = tc.y;
    const int tcx = min(G - 1, max(0, (int)(tx * CELLI)));
    const int tcy = min(G - 1, max(0, (int)(ty * CELLI)));

    // ---- gather 3x3 cell info: one int4 count load per cell ----
    int cb[9]; int cnt[9]; unsigned ps[9];   // ps: packed sub-prefixes (3 x 7-bit)
    #pragma unroll
    for (int j = 0; j < 9; j++) {
        int x = tcx + (j % 3) - 1;
        int y = tcy + (j / 3) - 1;
        bool ok = (x >= 0) & (x < G) & (y >= 0) & (y < G);
        int c = ok ? (y * G + x) : 0;
        cb[j] = c * CAP;
        int4 q = ok ? __ldg(reinterpret_cast<const int4*>(g_count + c * R))
                    : make_int4(0, 0, 0, 0);
        int c0 = min(q.x, SUB), c1 = min(q.y, SUB);
        int c2 = min(q.z, SUB), c3 = min(q.w, SUB);
        int a1 = c0, a2 = c0 + c1, a3 = c0 + c1 + c2;
        cnt[j] = a3 + c3;
        ps[j] = (unsigned)a1 | ((unsigned)a2 << 7) | ((unsigned)a3 << 14);
    }
    int pref[10];
    pref[0] = 0;
    #pragma unroll
    for (int j = 0; j < 9; j++) pref[j + 1] = pref[j] + cnt[j];
    const int T = pref[9];

    unsigned long long sel = ~0ull;
    bool stop = false;

    if (T <= 32 * CHUNK) {
        // ---- hot path: single-pass load, lane sort, REDUX extraction ----
        unsigned long long key[CHUNK];
        {
            float4 pts[CHUNK]; bool val[CHUNK];
            #pragma unroll
            for (int c = 0; c < CHUNK; c++) {
                int v = c * 32 + lane;
                val[c] = (v < T);
                // hierarchical map: 8-step cell select (base, prefix, packed sub-prefix)
                int basei = cb[0], pr = 0; unsigned pk = ps[0];
                #pragma unroll
                for (int jj = 1; jj < 9; jj++) {
                    bool ge = (v >= pref[jj]);
                    basei = ge ? cb[jj]   : basei;
                    pr    = ge ? pref[jj] : pr;
                    pk    = ge ? ps[jj]   : pk;
                }
                int u  = v - pr;
                int a1 = (int)(pk & 127u);
                int a2 = (int)((pk >> 7) & 127u);
                int a3 = (int)((pk >> 14) & 127u);
                int sub  = (u >= a1) + (u >= a2) + (u >= a3);
                int s_pr = (sub == 0) ? 0 : ((sub == 1) ? a1 : ((sub == 2) ? a2 : a3));
                int addr = basei + sub * SUB + (u - s_pr);
                if (val[c]) pts[c] = __ldg(&g_cells[addr]);   // independent LDGs, high MLP
            }
            #pragma unroll
            for (int c = 0; c < CHUNK; c++) {
                if (val[c]) {
                    float dx = tx - pts[c].x;
                    float dy = ty - pts[c].y;
                    float d2 = fmaf(dy, dy, dx * dx);   // identical fp expr to verified kernels
                    key[c] = ((unsigned long long)__float_as_uint(d2) << 32)
                           | (unsigned)__float_as_int(pts[c].z);
                } else {
                    key[c] = ~0ull;                     // pad sorts last
                }
            }
        }

        // optimal 12-CE sorting network for 6 elements (ascending)
        auto CE = [&](int a, int b) {
            unsigned long long ka = key[a], kb = key[b];
            key[a] = ka < kb ? ka : kb;
            key[b] = ka < kb ? kb : ka;
        };
        CE(1,2); CE(4,5); CE(0,2); CE(3,5); CE(0,1); CE(3,4);
        CE(2,5); CE(0,3); CE(1,4); CE(2,4); CE(1,3); CE(2,3);

        // 9 extraction rounds: exact lex-min via two hardware REDUX.MIN ops
        unsigned D9bits = 0xFFFFFFFFu;
        #pragma unroll
        for (int r = 0; r < K; r++) {
            unsigned hi = (unsigned)(key[0] >> 32);
            unsigned lo = (unsigned)key[0];
            unsigned m1 = __reduce_min_sync(FULLMASK, hi);
            unsigned iv = (hi == m1) ? lo : 0xFFFFFFFFu;
            unsigned m2 = __reduce_min_sync(FULLMASK, iv);
            if (lane == r) sel = ((unsigned long long)m1 << 32) | m2;
            if (r == K - 1) D9bits = m1;
            if (hi == m1 && lo == m2) {     // unique owner for real keys
                #pragma unroll
                for (int j = 0; j < CHUNK - 1; j++) key[j] = key[j + 1];
                key[CHUNK - 1] = ~0ull;
            }
        }

        // r=1 stop bound (conservative). NaN/INF D9 -> stop stays false -> fallback.
        float D9 = __uint_as_float(D9bits);
        int x0 = max(tcx - 1, 0), x1 = min(tcx + 1, G - 1);
        int y0 = max(tcy - 1, 0), y1 = min(tcy + 1, G - 1);
        float m = INF;
        if (x0 > 0)     m = fminf(m, tx - (float)x0 * CELL);
        if (x1 < G - 1) m = fminf(m, (float)(x1 + 1) * CELL - tx);
        if (y0 > 0)     m = fminf(m, ty - (float)y0 * CELL);
        if (y1 < G - 1) m = fminf(m, (float)(y1 + 1) * CELL - ty);
        m *= 0.999f;
        stop = (m > 0.f && m * m > D9);
    }

    if (!stop) {
        // ---- fallback: box rescan from scratch, lane-per-cell (cold) ----
        float bd[K]; int bi[K];

        auto insertPt = [&](float4 c) {
            float dx = tx - c.x;
            float dy = ty - c.y;
            float d2 = fmaf(dy, dy, dx * dx);
            int   ci = __float_as_int(c.z);
            if (d2 < bd[K - 1] || (d2 == bd[K - 1] && ci < bi[K - 1])) {
                float cd = d2; int cj = ci;
                #pragma unroll
                for (int j = 0; j < K; j++) {
                    bool lt = (cd < bd[j]) || (cd == bd[j] && cj < bi[j]);
                    if (lt) {
                        float td = bd[j]; bd[j] = cd; cd = td;
                        int   ti = bi[j]; bi[j] = cj; cj = ti;
                    }
                }
            }
        };
        auto merge = [&]() {
            unsigned long long kk[K];
            #pragma unroll
            for (int j = 0; j < K; j++)
                kk[j] = ((unsigned long long)__float_as_uint(bd[j]) << 32) | (unsigned)bi[j];
            unsigned long long cur = kk[0];
            #pragma unroll
            for (int r = 0; r < K; r++) {
                unsigned long long mm = cur;
                #pragma unroll
                for (int o = 16; o; o >>= 1) {
                    unsigned long long v = __shfl_xor_sync(FULLMASK, mm, o);
                    if (v < mm) mm = v;
                }
                if (lane == r) sel = mm;
                if (cur == mm) {
                    #pragma unroll
                    for (int j = 0; j < K - 1; j++) kk[j] = kk[j + 1];
                    kk[K - 1] = ~0ull;
                    cur = kk[0];
                }
            }
        };

        for (int r = 2; ; r++) {
            int x0 = max(tcx - r, 0), x1 = min(tcx + r, G - 1);
            int y0 = max(tcy - r, 0), y1 = min(tcy + r, G - 1);
            int W = x1 - x0 + 1;
            int ncells = W * (y1 - y0 + 1);

            #pragma unroll
            for (int j = 0; j < K; j++) { bd[j] = INF; bi[j] = 0x7fffffff; }

            for (int cc = lane; cc < ncells; cc += 32) {
                int cy = y0 + cc / W;
                int cx2 = x0 + cc % W;
                int cell = cy * G + cx2;
                int4 q = __ldg(reinterpret_cast<const int4*>(g_count + cell * R));
                const float4* bp = g_cells + cell * CAP;
                #pragma unroll
                for (int rr = 0; rr < R; rr++) {
                    int cn = min(rr == 0 ? q.x : rr == 1 ? q.y : rr == 2 ? q.z : q.w, SUB);
                    const float4* sp = bp + rr * SUB;
                    int s = 0;
                    for (; s + 2 <= cn; s += 2) {
                        float4 p0 = __ldg(sp + s);
                        float4 p1 = __ldg(sp + s + 1);
                        insertPt(p0); insertPt(p1);
                    }
                    for (; s < cn; s++) insertPt(__ldg(sp + s));
                }
            }

            merge();
            if (x0 == 0 && y0 == 0 && x1 == G - 1 && y1 == G - 1) break;  // full grid
            unsigned d9b = __shfl_sync(FULLMASK, (unsigned)(sel >> 32), 8);
            float D9f = __uint_as_float(d9b);
            float mf = INF;
            if (x0 > 0)     mf = fminf(mf, tx - (float)x0 * CELL);
            if (x1 < G - 1) mf = fminf(mf, (float)(x1 + 1) * CELL - tx);
            if (y0 > 0)     mf = fminf(mf, ty - (float)y0 * CELL);
            if (y1 < G - 1) mf = fminf(mf, (float)(y1 + 1) * CELL - ty);
            mf *= 0.999f;    // conservative margin; false on NaN/INF -> keep expanding
            if (mf > 0.f && mf * mf > D9f) break;
        }
    }

    // ---- epilogue: GIoU + mean/var(ddof=1) threshold (bit-identical fp order) ----
    float gx = tx, gy = ty;
    float gw = ts.x, gh = ts.y;

    float cx = 0.f, cy = 0.f, cw_ = 0.f, ch_ = 0.f;
    if (lane < K) {
        int idx = (int)(sel & 0xffffffffull);
        float2 pc = *reinterpret_cast<const float2*>(pbox + (size_t)idx * 6 + 2);
        float2 psz = *reinterpret_cast<const float2*>(pbox + (size_t)idx * 6 + 4);
        cx = pc.x; cy = pc.y; cw_ = psz.x; ch_ = psz.y;
    }

    float b1x1 = gx - gw * 0.5f, b1x2 = gx + gw * 0.5f;
    float b1y1 = gy - gh * 0.5f, b1y2 = gy + gh * 0.5f;
    float b2x1 = cx - cw_ * 0.5f, b2x2 = cx + cw_ * 0.5f;
    float b2y1 = cy - ch_ * 0.5f, b2y2 = cy + ch_ * 0.5f;
    float iw = fmaxf(fminf(b1x2, b2x2) - fmaxf(b1x1, b2x1), 0.f);
    float ih = fmaxf(fminf(b1y2, b2y2) - fmaxf(b1y1, b2y1), 0.f);
    float inter = iw * ih;
    float w1 = b1x2 - b1x1, h1 = b1y2 - b1y1;
    float w2 = b2x2 - b2x1, h2 = b2y2 - b2y1;
    float uni = ((w1 * h1 + 1e-16f) + w2 * h2) - inter;
    float iou = __fdiv_rn(inter, uni);
    float ccw = fmaxf(b1x2, b2x2) - fminf(b1x1, b2x1);
    float cch = fmaxf(b1y2, b2y2) - fminf(b1y1, b2y1);
    float carea = ccw * cch + 1e-16f;
    float g = iou - __fdiv_rn(carea - uni, carea);

    float s = 0.f;
    #pragma unroll
    for (int j = 0; j < K; j++) s += __shfl_sync(FULLMASK, g, j);
    float mean = __fdiv_rn(s, 9.0f);
    float v = 0.f;
    #pragma unroll
    for (int j = 0; j < K; j++) {
        float gj = __shfl_sync(FULLMASK, g, j);
        float d = gj - mean;
        v += d * d;
    }
    float var = __fdiv_rn(v, 8.0f);
    float thr = mean + var;

    if (lane < K) {
        float msk = (g > thr) ? 1.0f : 0.0f;
        float4 o = make_float4(cx * msk, cy * msk, cw_ * msk, ch_ * msk);
        *reinterpret_cast<float4*>(out + ((size_t)t * K + lane) * 4) = o;
    }
}

extern "C" void kernel_launch(void* const* d_in, const int* in_sizes, int n_in,
                              void* d_out, int out_size) {
    const float* pbox = (const float*)d_in[0];
    const float* tgt  = (const float*)d_in[1];
    int N  = in_sizes[0] / 6;
    int NT = in_sizes[1] / 6;

    void* cnt_ptr = nullptr;
    cudaGetSymbolAddress(&cnt_ptr, g_count);
    cudaMemsetAsync(cnt_ptr, 0, NC * R * sizeof(int));   // memset node, graph-capturable

    int half = (N + 1) >> 1;
    bin_k<<<(half + 63) / 64, 64>>>(pbox, N);

    int blocks = (NT + WARPS - 1) / WARPS;
    atss_search_k<<<blocks, WARPS * 32>>>(pbox, tgt, (float*)d_out, NT);
}

// round 10
// speedup vs baseline: 1.0022x; 1.0022x over previous
#include <cuda_runtime.h>

#define FULLMASK 0xFFFFFFFFu

constexpr int   G     = 64;          // 64x64 grid of 16px cells
constexpr float CELL  = 16.0f;
constexpr float CELLI = 1.0f / 16.0f;
constexpr int   NC    = G * G;
constexpr int   R     = 2;           // replicated sub-counters per cell (contention /2)
constexpr int   SUB   = 40;          // capacity per replica; lambda=8 -> P(>40) ~ 1e-18
constexpr int   CAP   = R * SUB;     // 80 slots per cell
constexpr int   K     = 9;
constexpr int   WARPS = 2;
constexpr int   CHUNK = 6;           // 6*32 = 192 capacity; P(T>192) ~ 3e-5

__device__ int    g_count[NC * R];     // [cell][replica]
__device__ float4 g_cells[NC * CAP];   // x, y, bitcast(orig idx), pad

__global__ void bin_k(const float* __restrict__ p, int N) {
    int i = blockIdx.x * blockDim.x + threadIdx.x;
    if (i >= N) return;
    float2 c = reinterpret_cast<const float2*>(p)[i * 3 + 1];  // floats 6i+2, 6i+3
    int cx = min(G - 1, max(0, (int)(c.x * CELLI)));
    int cy = min(G - 1, max(0, (int)(c.y * CELLI)));
    int cell = cy * G + cx;
    int r = i & (R - 1);
    int pos = atomicAdd(&g_count[cell * R + r], 1);
    if (pos < SUB)
        g_cells[cell * CAP + r * SUB + pos] = make_float4(c.x, c.y, __int_as_float(i), 0.f);
}

__global__ __launch_bounds__(WARPS * 32, 8)
void atss_search_k(const float* __restrict__ pbox,
                   const float* __restrict__ tgt,
                   float* __restrict__ out, int NT)
{
    const int lane = threadIdx.x & 31;
    const int t = blockIdx.x * WARPS + (threadIdx.x >> 5);
    if (t >= NT) return;

    const float INF = __int_as_float(0x7f800000);
    float2 tc = *reinterpret_cast<const float2*>(tgt + t * 6 + 2);
    float2 ts = *reinterpret_cast<const float2*>(tgt + t * 6 + 4);
    const float tx = tc.x, ty = tc.y;
    const int tcx = min(G - 1, max(0, (int)(tx * CELLI)));
    const int tcy = min(G - 1, max(0, (int)(ty * CELLI)));

    // ---- gather 3x3 cell info: one aligned int2 count load per cell ----
    int cb[9]; int cnt[9]; int sa[9];   // sa: first-replica count (split point)
    #pragma unroll
    for (int j = 0; j < 9; j++) {
        int x = tcx + (j % 3) - 1;
        int y = tcy + (j / 3) - 1;
        bool ok = (x >= 0) & (x < G) & (y >= 0) & (y < G);
        int c = ok ? (y * G + x) : 0;
        cb[j] = c * CAP;
        int2 q = ok ? __ldg(reinterpret_cast<const int2*>(g_count + c * R))
                    : make_int2(0, 0);
        int c0 = min(q.x, SUB), c1 = min(q.y, SUB);
        cnt[j] = c0 + c1;
        sa[j]  = c0;
    }
    int pref[10];
    pref[0] = 0;
    #pragma unroll
    for (int j = 0; j < 9; j++) pref[j + 1] = pref[j] + cnt[j];
    const int T = pref[9];

    unsigned long long sel = ~0ull;
    bool stop = false;
    float cx = 0.f, cy = 0.f, cw_ = 0.f, ch_ = 0.f;   // epilogue candidate box

    if (T <= 32 * CHUNK) {
        // ---- hot path: batched loads, lane sort, REDUX extraction ----
        unsigned long long key[CHUNK];
        {
            float4 pts[CHUNK]; bool val[CHUNK];
            // map v -> address via 8-step select chain + 1-step replica split
            auto mapLoad = [&](int c) {
                int v = c * 32 + lane;
                val[c] = (v < T);
                int basei = cb[0], pr = 0, a1 = sa[0];
                #pragma unroll
                for (int jj = 1; jj < 9; jj++) {
                    bool ge = (v >= pref[jj]);
                    basei = ge ? cb[jj]   : basei;
                    pr    = ge ? pref[jj] : pr;
                    a1    = ge ? sa[jj]   : a1;
                }
                int u = v - pr;
                int addr = basei + ((u >= a1) ? (SUB + u - a1) : u);
                if (val[c]) pts[c] = __ldg(&g_cells[addr]);   // independent LDGs, high MLP
            };
            #pragma unroll
            for (int c = 0; c < 4; c++) mapLoad(c);
            if (T > 128) {              // warp-uniform: skip last 2 chunks when unneeded
                mapLoad(4); mapLoad(5);
            } else {
                val[4] = false; val[5] = false;
            }
            #pragma unroll
            for (int c = 0; c < CHUNK; c++) {
                if (val[c]) {
                    float dx = tx - pts[c].x;
                    float dy = ty - pts[c].y;
                    float d2 = fmaf(dy, dy, dx * dx);   // identical fp expr to verified kernels
                    key[c] = ((unsigned long long)__float_as_uint(d2) << 32)
                           | (unsigned)__float_as_int(pts[c].z);
                } else {
                    key[c] = ~0ull;                     // pad sorts last
                }
            }
        }

        // optimal 12-CE sorting network for 6 elements (ascending)
        auto CE = [&](int a, int b) {
            unsigned long long ka = key[a], kb = key[b];
            key[a] = ka < kb ? ka : kb;
            key[b] = ka < kb ? kb : ka;
        };
        CE(1,2); CE(4,5); CE(0,2); CE(3,5); CE(0,1); CE(3,4);
        CE(2,5); CE(0,3); CE(1,4); CE(2,4); CE(1,3); CE(2,3);

        // 9 extraction rounds: exact lex-min via two hardware REDUX.MIN ops.
        // Progressive prefetch: the selected candidate's epilogue box loads are
        // issued immediately (predicated), overlapping the remaining rounds.
        unsigned D9bits = 0xFFFFFFFFu;
        #pragma unroll
        for (int r = 0; r < K; r++) {
            unsigned hi = (unsigned)(key[0] >> 32);
            unsigned lo = (unsigned)key[0];
            unsigned m1 = __reduce_min_sync(FULLMASK, hi);
            unsigned iv = (hi == m1) ? lo : 0xFFFFFFFFu;
            unsigned m2 = __reduce_min_sync(FULLMASK, iv);
            if (lane == r) {
                sel = ((unsigned long long)m1 << 32) | m2;
                if ((int)m2 >= 0) {   // guard: sentinel idx (0xFFFFFFFF) -> no load
                    const float* bp = pbox + (size_t)m2 * 6;
                    float2 pc  = *reinterpret_cast<const float2*>(bp + 2);
                    float2 psz = *reinterpret_cast<const float2*>(bp + 4);
                    cx = pc.x; cy = pc.y; cw_ = psz.x; ch_ = psz.y;
                }
            }
            if (r == K - 1) D9bits = m1;
            if (hi == m1 && lo == m2) {     // unique owner for real keys
                #pragma unroll
                for (int j = 0; j < CHUNK - 1; j++) key[j] = key[j + 1];
                key[CHUNK - 1] = ~0ull;
            }
        }

        // r=1 stop bound (conservative). NaN/INF D9 -> stop stays false -> fallback.
        float D9 = __uint_as_float(D9bits);
        int x0 = max(tcx - 1, 0), x1 = min(tcx + 1, G - 1);
        int y0 = max(tcy - 1, 0), y1 = min(tcy + 1, G - 1);
        float m = INF;
        if (x0 > 0)     m = fminf(m, tx - (float)x0 * CELL);
        if (x1 < G - 1) m = fminf(m, (float)(x1 + 1) * CELL - tx);
        if (y0 > 0)     m = fminf(m, ty - (float)y0 * CELL);
        if (y1 < G - 1) m = fminf(m, (float)(y1 + 1) * CELL - ty);
        m *= 0.999f;
        stop = (m > 0.f && m * m > D9);
    }

    if (!stop) {
        // ---- fallback: box rescan from scratch, lane-per-cell (cold) ----
        float bd[K]; int bi[K];

        auto insertPt = [&](float4 c) {
            float dx = tx - c.x;
            float dy = ty - c.y;
            float d2 = fmaf(dy, dy, dx * dx);
            int   ci = __float_as_int(c.z);
            if (d2 < bd[K - 1] || (d2 == bd[K - 1] && ci < bi[K - 1])) {
                float cd = d2; int cj = ci;
                #pragma unroll
                for (int j = 0; j < K; j++) {
                    bool lt = (cd < bd[j]) || (cd == bd[j] && cj < bi[j]);
                    if (lt) {
                        float td = bd[j]; bd[j] = cd; cd = td;
                        int   ti = bi[j]; bi[j] = cj; cj = ti;
                    }
                }
            }
        };
        auto merge = [&]() {
            unsigned long long kk[K];
            #pragma unroll
            for (int j = 0; j < K; j++)
                kk[j] = ((unsigned long long)__float_as_uint(bd[j]) << 32) | (unsigned)bi[j];
            unsigned long long cur = kk[0];
            #pragma unroll
            for (int r = 0; r < K; r++) {
                unsigned long long mm = cur;
                #pragma unroll
                for (int o = 16; o; o >>= 1) {
                    unsigned long long v = __shfl_xor_sync(FULLMASK, mm, o);
                    if (v < mm) mm = v;
                }
                if (lane == r) sel = mm;
                if (cur == mm) {
                    #pragma unroll
                    for (int j = 0; j < K - 1; j++) kk[j] = kk[j + 1];
                    kk[K - 1] = ~0ull;
                    cur = kk[0];
                }
            }
        };

        for (int r = 2; ; r++) {
            int x0 = max(tcx - r, 0), x1 = min(tcx + r, G - 1);
            int y0 = max(tcy - r, 0), y1 = min(tcy + r, G - 1);
            int W = x1 - x0 + 1;
            int ncells = W * (y1 - y0 + 1);

            #pragma unroll
            for (int j = 0; j < K; j++) { bd[j] = INF; bi[j] = 0x7fffffff; }

            for (int cc = lane; cc < ncells; cc += 32) {
                int yy = y0 + cc / W;
                int xx = x0 + cc % W;
                int cell = yy * G + xx;
                int2 q = __ldg(reinterpret_cast<const int2*>(g_count + cell * R));
                const float4* bp = g_cells + cell * CAP;
                #pragma unroll
                for (int rr = 0; rr < R; rr++) {
                    int cn = min(rr == 0 ? q.x : q.y, SUB);
                    const float4* sp = bp + rr * SUB;
                    int s = 0;
                    for (; s + 2 <= cn; s += 2) {
                        float4 p0 = __ldg(sp + s);
                        float4 p1 = __ldg(sp + s + 1);
                        insertPt(p0); insertPt(p1);
                    }
                    for (; s < cn; s++) insertPt(__ldg(sp + s));
                }
            }

            merge();
            if (x0 == 0 && y0 == 0 && x1 == G - 1 && y1 == G - 1) break;  // full grid
            unsigned d9b = __shfl_sync(FULLMASK, (unsigned)(sel >> 32), 8);
            float D9f = __uint_as_float(d9b);
            float mf = INF;
            if (x0 > 0)     mf = fminf(mf, tx - (float)x0 * CELL);
            if (x1 < G - 1) mf = fminf(mf, (float)(x1 + 1) * CELL - tx);
            if (y0 > 0)     mf = fminf(mf, ty - (float)y0 * CELL);
            if (y1 < G - 1) mf = fminf(mf, (float)(y1 + 1) * CELL - ty);
            mf *= 0.999f;    // conservative margin; false on NaN/INF -> keep expanding
            if (mf > 0.f && mf * mf > D9f) break;
        }

        // fallback epilogue gather (hot path already prefetched its boxes)
        if (lane < K) {
            int idx = (int)(sel & 0xffffffffull);
            float2 pc  = *reinterpret_cast<const float2*>(pbox + (size_t)idx * 6 + 2);
            float2 psz = *reinterpret_cast<const float2*>(pbox + (size_t)idx * 6 + 4);
            cx = pc.x; cy = pc.y; cw_ = psz.x; ch_ = psz.y;
        } else {
            cx = 0.f; cy = 0.f; cw_ = 0.f; ch_ = 0.f;
        }
    }

    // ---- epilogue: GIoU + mean/var(ddof=1) threshold (bit-identical fp order) ----
    float gx = tx, gy = ty;
    float gw = ts.x, gh = ts.y;

    float b1x1 = gx - gw * 0.5f, b1x2 = gx + gw * 0.5f;
    float b1y1 = gy - gh * 0.5f, b1y2 = gy + gh * 0.5f;
    float b2x1 = cx - cw_ * 0.5f, b2x2 = cx + cw_ * 0.5f;
    float b2y1 = cy - ch_ * 0.5f, b2y2 = cy + ch_ * 0.5f;
    float iw = fmaxf(fminf(b1x2, b2x2) - fmaxf(b1x1, b2x1), 0.f);
    float ih = fmaxf(fminf(b1y2, b2y2) - fmaxf(b1y1, b2y1), 0.f);
    float inter = iw * ih;
    float w1 = b1x2 - b1x1, h1 = b1y2 - b1y1;
    float w2 = b2x2 - b2x1, h2 = b2y2 - b2y1;
    float uni = ((w1 * h1 + 1e-16f) + w2 * h2) - inter;
    float iou = __fdiv_rn(inter, uni);
    float ccw = fmaxf(b1x2, b2x2) - fminf(b1x1, b2x1);
    float cch = fmaxf(b1y2, b2y2) - fminf(b1y1, b2y1);
    float carea = ccw * cch + 1e-16f;
    float g = iou - __fdiv_rn(carea - uni, carea);

    float s = 0.f;
    #pragma unroll
    for (int j = 0; j < K; j++) s += __shfl_sync(FULLMASK, g, j);
    float mean = __fdiv_rn(s, 9.0f);
    float v = 0.f;
    #pragma unroll
    for (int j = 0; j < K; j++) {
        float gj = __shfl_sync(FULLMASK, g, j);
        float d = gj - mean;
        v += d * d;
    }
    float var = __fdiv_rn(v, 8.0f);
    float thr = mean + var;

    if (lane < K) {
        float msk = (g > thr) ? 1.0f : 0.0f;
        float4 o = make_float4(cx * msk, cy * msk, cw_ * msk, ch_ * msk);
        *reinterpret_cast<float4*>(out + ((size_t)t * K + lane) * 4) = o;
    }
}

extern "C" void kernel_launch(void* const* d_in, const int* in_sizes, int n_in,
                              void* d_out, int out_size) {
    const float* pbox = (const float*)d_in[0];
    const float* tgt  = (const float*)d_in[1];
    int N  = in_sizes[0] / 6;
    int NT = in_sizes[1] / 6;

    void* cnt_ptr = nullptr;
    cudaGetSymbolAddress(&cnt_ptr, g_count);
    cudaMemsetAsync(cnt_ptr, 0, NC * R * sizeof(int));   // memset node, graph-capturable

    bin_k<<<(N + 255) / 256, 256>>>(pbox, N);

    int blocks = (NT + WARPS - 1) / WARPS;
    atss_search_k<<<blocks, WARPS * 32>>>(pbox, tgt, (float*)d_out, NT);
}